// round 14
// baseline (speedup 1.0000x reference)
#include <cuda_runtime.h>
#include <cuda_bf16.h>

// Contrastive loss v12 = v3 (best, 16.45us) with ZERO-COST software pipelining:
// after the FMA block consumes va/vb into s, those 32 registers are dead ->
// issue the NEXT pair's 8 row loads into the SAME registers BEFORE the
// 5-SHFL reduce chain + loss math. The ~180-cycle reduce tail now overlaps
// outstanding loads instead of leaving the memory system idle.
// launch_bounds(256,7) caps regs at 36 so occupancy stays >=84% (R10 guard).
//
//   per pair p: sq = ||emb[a]-emb[b]||^2 ; d = sqrt(max(sq,1e-12))
//   loss_p = (1-i)*max(0,1-d)^2 + i*d^2 ; out = sum / (P+1e-10)

#define D_DIM 512
#define VEC_PER_ROW (D_DIM / 4)      // 128 float4 per row
#define WARPS_PER_BLOCK 8
#define THREADS_PER_BLOCK (WARPS_PER_BLOCK * 32)
#define BLOCKS_TARGET 1024           // measured-best config
#define MAX_BLOCKS 16384

__device__ float        g_partials[MAX_BLOCKS];
__device__ unsigned int g_counter = 0;

__device__ __forceinline__ unsigned int atom_add_acqrel(unsigned int* p,
                                                        unsigned int v) {
    unsigned int old;
    asm volatile("atom.acq_rel.gpu.global.add.u32 %0, [%1], %2;"
                 : "=r"(old) : "l"(p), "r"(v) : "memory");
    return old;
}

__global__ __launch_bounds__(THREADS_PER_BLOCK, 7)
void contrastive_fused_kernel(const float* __restrict__ emb,
                              const int* __restrict__ pair_a,
                              const int* __restrict__ pair_b,
                              const int* __restrict__ pair_same,
                              float* __restrict__ out,
                              int P)
{
    const int warp_id     = threadIdx.x >> 5;
    const int lane        = threadIdx.x & 31;
    const int warp_global = blockIdx.x * WARPS_PER_BLOCK + warp_id;
    const int warp_stride = gridDim.x * WARPS_PER_BLOCK;

    const float4* __restrict__ embv = reinterpret_cast<const float4*>(emb);

    float warp_loss = 0.0f;   // meaningful on lane 0 only

    // Prologue: indices for pair p and p+stride, rows for pair p.
    int p      = warp_global;
    int p_next = p + warp_stride;
    int ia_n = 0, ib_n = 0;
    if (p_next < P) { ia_n = __ldg(pair_a + p_next); ib_n = __ldg(pair_b + p_next); }

    float4 va[4], vb[4];
    if (p < P) {
        const int ia = __ldg(pair_a + p);
        const int ib = __ldg(pair_b + p);
        const float4* __restrict__ ra = embv + (size_t)ia * VEC_PER_ROW;
        const float4* __restrict__ rb = embv + (size_t)ib * VEC_PER_ROW;
        #pragma unroll
        for (int k = 0; k < 4; ++k) {
            va[k] = __ldcg(ra + lane + k * 32);
            vb[k] = __ldcg(rb + lane + k * 32);
        }
    }

    while (p < P) {
        // 1) Consume current rows into s (va/vb die here).
        float s = 0.0f;
        #pragma unroll
        for (int k = 0; k < 4; ++k) {
            float dx = va[k].x - vb[k].x;
            float dy = va[k].y - vb[k].y;
            float dz = va[k].z - vb[k].z;
            float dw = va[k].w - vb[k].w;
            s += dx * dx + dy * dy + dz * dz + dw * dw;
        }

        // 2) Issue NEXT pair's row loads into the (dead) va/vb registers —
        //    these stay in flight through the reduce chain below.
        if (p_next < P) {
            const float4* __restrict__ ra = embv + (size_t)ia_n * VEC_PER_ROW;
            const float4* __restrict__ rb = embv + (size_t)ib_n * VEC_PER_ROW;
            #pragma unroll
            for (int k = 0; k < 4; ++k) {
                va[k] = __ldcg(ra + lane + k * 32);
                vb[k] = __ldcg(rb + lane + k * 32);
            }
        }

        // 3) Prefetch indices for the pair after next.
        const int p_nn = p_next + warp_stride;
        if (p_nn < P) { ia_n = __ldg(pair_a + p_nn); ib_n = __ldg(pair_b + p_nn); }

        // 4) Reduce + loss for pair p (overlaps the in-flight loads).
        #pragma unroll
        for (int off = 16; off > 0; off >>= 1)
            s += __shfl_xor_sync(0xFFFFFFFFu, s, off);

        if (lane == 0) {
            float d = sqrtf(fmaxf(s, 1e-12f));
            float i = (float)__ldg(pair_same + p);
            float h = fmaxf(0.0f, 1.0f - d);
            warp_loss += (1.0f - i) * h * h + i * d * d;
        }

        p = p_next; p_next = p_nn;
    }

    // Block reduction of per-warp losses.
    __shared__ float s_loss[WARPS_PER_BLOCK];
    __shared__ bool  s_is_last;
    if (lane == 0) s_loss[warp_id] = warp_loss;
    __syncthreads();

    if (threadIdx.x == 0) {
        float acc = 0.0f;
        #pragma unroll
        for (int w = 0; w < WARPS_PER_BLOCK; ++w) acc += s_loss[w];
        g_partials[blockIdx.x] = acc;
        unsigned int prev = atom_add_acqrel(&g_counter, 1u);  // release-orders store
        s_is_last = (prev == gridDim.x - 1);
        if (s_is_last) atomicExch(&g_counter, 0u);  // replay-safe self-reset
    }
    __syncthreads();

    // Last block: deterministic final reduction in fixed index order.
    if (s_is_last) {
        __shared__ float s_fin[THREADS_PER_BLOCK];
        float acc = 0.0f;
        for (int i = threadIdx.x; i < (int)gridDim.x; i += THREADS_PER_BLOCK)
            acc += g_partials[i];
        s_fin[threadIdx.x] = acc;
        __syncthreads();
        #pragma unroll
        for (int off = THREADS_PER_BLOCK / 2; off > 0; off >>= 1) {
            if (threadIdx.x < off) s_fin[threadIdx.x] += s_fin[threadIdx.x + off];
            __syncthreads();
        }
        if (threadIdx.x == 0)
            out[0] = s_fin[0] / ((float)P + 1e-10f);
    }
}

extern "C" void kernel_launch(void* const* d_in, const int* in_sizes, int n_in,
                              void* d_out, int out_size)
{
    const float* emb       = (const float*)d_in[0];
    const int*   pair_a    = (const int*)d_in[1];
    const int*   pair_b    = (const int*)d_in[2];
    const int*   pair_same = (const int*)d_in[3];
    float*       out       = (float*)d_out;

    const int P = in_sizes[1];  // element count of pair_a

    // Measured-best single wave: 1024 blocks, 4 pairs/warp at P=32768.
    int warps_needed = (P + 3) / 4;
    int num_blocks = (warps_needed + WARPS_PER_BLOCK - 1) / WARPS_PER_BLOCK;
    if (num_blocks > BLOCKS_TARGET) num_blocks = BLOCKS_TARGET;
    if (num_blocks < 1) num_blocks = 1;

    contrastive_fused_kernel<<<num_blocks, THREADS_PER_BLOCK>>>(
        emb, pair_a, pair_b, pair_same, out, P);
}

// round 15
// speedup vs baseline: 2.1659x; 2.1659x over previous
#include <cuda_runtime.h>
#include <cuda_bf16.h>

// Contrastive loss FINAL (v13) = v3 exactly (measured best, 16.45us) with one
// micro-tweak: pair_same is prefetched alongside the pair indices instead of
// being a dependent scalar load on lane 0's post-reduce tail.
//
// Round history established v3 as the memory-service floor for this pattern:
//  - register double-buffer (R6), batched reduces (R7), LDG.256 (R10),
//    cp.async ring (R11): all lost occupancy-MLP and regressed
//  - occupancy 84->95% (R12): neutral -> plateau above ~84%
//  - evict_last (R9): neutral -> L2 residency not kernel-controllable here
//  - reg-capped pipeline (R14): spilled to local, 2.6x regression
//
//   per pair p: sq = ||emb[a]-emb[b]||^2 ; d = sqrt(max(sq,1e-12))
//   loss_p = (1-i)*max(0,1-d)^2 + i*d^2 ; out = sum / (P+1e-10)

#define D_DIM 512
#define VEC_PER_ROW (D_DIM / 4)      // 128 float4 per row
#define WARPS_PER_BLOCK 8
#define THREADS_PER_BLOCK (WARPS_PER_BLOCK * 32)
#define BLOCKS_TARGET 1024           // measured-best single balanced wave
#define MAX_BLOCKS 16384

__device__ float        g_partials[MAX_BLOCKS];
__device__ unsigned int g_counter = 0;

__device__ __forceinline__ unsigned int atom_add_acqrel(unsigned int* p,
                                                        unsigned int v) {
    unsigned int old;
    asm volatile("atom.acq_rel.gpu.global.add.u32 %0, [%1], %2;"
                 : "=r"(old) : "l"(p), "r"(v) : "memory");
    return old;
}

__global__ __launch_bounds__(THREADS_PER_BLOCK)
void contrastive_fused_kernel(const float* __restrict__ emb,
                              const int* __restrict__ pair_a,
                              const int* __restrict__ pair_b,
                              const int* __restrict__ pair_same,
                              float* __restrict__ out,
                              int P)
{
    const int warp_id     = threadIdx.x >> 5;
    const int lane        = threadIdx.x & 31;
    const int warp_global = blockIdx.x * WARPS_PER_BLOCK + warp_id;
    const int warp_stride = gridDim.x * WARPS_PER_BLOCK;

    const float4* __restrict__ embv = reinterpret_cast<const float4*>(emb);

    float warp_loss = 0.0f;   // meaningful on lane 0 only

    int p  = warp_global;
    int ia = 0, ib = 0, is = 0;
    if (p < P) {
        ia = __ldg(pair_a + p);
        ib = __ldg(pair_b + p);
        is = __ldg(pair_same + p);
    }

    while (p < P) {
        // Prefetch next pair's indices AND same-flag (hides idx->row chain
        // and removes the dependent scalar load from the loss tail).
        const int p_next = p + warp_stride;
        int ia_next = 0, ib_next = 0, is_next = 0;
        if (p_next < P) {
            ia_next = __ldg(pair_a + p_next);
            ib_next = __ldg(pair_b + p_next);
            is_next = __ldg(pair_same + p_next);
        }

        const float4* __restrict__ ra = embv + (size_t)ia * VEC_PER_ROW;
        const float4* __restrict__ rb = embv + (size_t)ib * VEC_PER_ROW;

        // 8 independent 16B L2-only loads (512B/warp each, fully coalesced).
        float4 va[4], vb[4];
        #pragma unroll
        for (int k = 0; k < 4; ++k) {
            va[k] = __ldcg(ra + lane + k * 32);
            vb[k] = __ldcg(rb + lane + k * 32);
        }

        // ||a-b||^2 per lane.
        float s = 0.0f;
        #pragma unroll
        for (int k = 0; k < 4; ++k) {
            float dx = va[k].x - vb[k].x;
            float dy = va[k].y - vb[k].y;
            float dz = va[k].z - vb[k].z;
            float dw = va[k].w - vb[k].w;
            s += dx * dx + dy * dy + dz * dz + dw * dw;
        }

        // Warp tree reduction (5 shfl).
        #pragma unroll
        for (int off = 16; off > 0; off >>= 1)
            s += __shfl_xor_sync(0xFFFFFFFFu, s, off);

        if (lane == 0) {
            float sq = fmaxf(s, 1e-12f);
            float d = sqrtf(sq);
            float i = (float)is;            // already in a register
            float h = fmaxf(0.0f, 1.0f - d);
            warp_loss += (1.0f - i) * h * h + i * d * d;
        }

        p  = p_next;
        ia = ia_next;
        ib = ib_next;
        is = is_next;
    }

    // Block reduction of per-warp losses.
    __shared__ float s_loss[WARPS_PER_BLOCK];
    __shared__ bool  s_is_last;
    if (lane == 0) s_loss[warp_id] = warp_loss;
    __syncthreads();

    if (threadIdx.x == 0) {
        float acc = 0.0f;
        #pragma unroll
        for (int w = 0; w < WARPS_PER_BLOCK; ++w) acc += s_loss[w];
        g_partials[blockIdx.x] = acc;
        unsigned int prev = atom_add_acqrel(&g_counter, 1u);  // release-orders store
        s_is_last = (prev == gridDim.x - 1);
        if (s_is_last) atomicExch(&g_counter, 0u);  // replay-safe self-reset
    }
    __syncthreads();

    // Last block: deterministic final reduction in fixed index order.
    if (s_is_last) {
        __shared__ float s_fin[THREADS_PER_BLOCK];
        float acc = 0.0f;
        for (int i = threadIdx.x; i < (int)gridDim.x; i += THREADS_PER_BLOCK)
            acc += g_partials[i];
        s_fin[threadIdx.x] = acc;
        __syncthreads();
        #pragma unroll
        for (int off = THREADS_PER_BLOCK / 2; off > 0; off >>= 1) {
            if (threadIdx.x < off) s_fin[threadIdx.x] += s_fin[threadIdx.x + off];
            __syncthreads();
        }
        if (threadIdx.x == 0)
            out[0] = s_fin[0] / ((float)P + 1e-10f);
    }
}

extern "C" void kernel_launch(void* const* d_in, const int* in_sizes, int n_in,
                              void* d_out, int out_size)
{
    const float* emb       = (const float*)d_in[0];
    const int*   pair_a    = (const int*)d_in[1];
    const int*   pair_b    = (const int*)d_in[2];
    const int*   pair_same = (const int*)d_in[3];
    float*       out       = (float*)d_out;

    const int P = in_sizes[1];  // element count of pair_a

    // Measured-best single wave: 1024 blocks, 4 pairs/warp at P=32768.
    int warps_needed = (P + 3) / 4;
    int num_blocks = (warps_needed + WARPS_PER_BLOCK - 1) / WARPS_PER_BLOCK;
    if (num_blocks > BLOCKS_TARGET) num_blocks = BLOCKS_TARGET;
    if (num_blocks < 1) num_blocks = 1;

    contrastive_fused_kernel<<<num_blocks, THREADS_PER_BLOCK>>>(
        emb, pair_a, pair_b, pair_same, out, P);
}

// round 16
// speedup vs baseline: 2.5864x; 1.1942x over previous
#include <cuda_runtime.h>
#include <cuda_bf16.h>

// Contrastive loss FINAL = v3 verbatim (measured best: 16.448us @ R5).
//   per pair p: a = emb[pair_a[p]], b = emb[pair_b[p]]  (rows of D=512 floats)
//   sq = ||a-b||^2 ; d = sqrt(max(sq,1e-12))
//   loss_p = (1-i)*max(0, 1-d)^2 + i*d^2 ; out = sum / (P + 1e-10)
//
// Search summary (15 rounds): this kernel sits on the memory-service floor
// for a random 2KB-row gather (~128MB at ~7.8 TB/s effective) AND on the
// 32-register/84%-occupancy knife edge. Every structural alternative was
// measured and regressed or was neutral:
//   reg double-buffer(R6) / batched reduces(R7) / LDG.256(R10) /
//   cp.async ring(R11) / reg-capped pipeline(R14): occupancy loss or spill
//   occ 95%(R12), evict_last(R9): neutral
//   any extra live scalar(R15): +6 regs -> occ 66% -> regression
// Do not perturb the loop body.

#define D_DIM 512
#define VEC_PER_ROW (D_DIM / 4)      // 128 float4 per row
#define WARPS_PER_BLOCK 8
#define THREADS_PER_BLOCK (WARPS_PER_BLOCK * 32)
#define BLOCKS_TARGET 1024           // 8192 warps -> 4 pairs/warp at P=32768
#define MAX_BLOCKS 16384

__device__ float        g_partials[MAX_BLOCKS];
__device__ unsigned int g_counter = 0;

__device__ __forceinline__ unsigned int atom_add_acqrel(unsigned int* p,
                                                        unsigned int v) {
    unsigned int old;
    asm volatile("atom.acq_rel.gpu.global.add.u32 %0, [%1], %2;"
                 : "=r"(old) : "l"(p), "r"(v) : "memory");
    return old;
}

__global__ __launch_bounds__(THREADS_PER_BLOCK)
void contrastive_fused_kernel(const float* __restrict__ emb,
                              const int* __restrict__ pair_a,
                              const int* __restrict__ pair_b,
                              const int* __restrict__ pair_same,
                              float* __restrict__ out,
                              int P)
{
    const int warp_id     = threadIdx.x >> 5;
    const int lane        = threadIdx.x & 31;
    const int warp_global = blockIdx.x * WARPS_PER_BLOCK + warp_id;
    const int warp_stride = gridDim.x * WARPS_PER_BLOCK;

    const float4* __restrict__ embv = reinterpret_cast<const float4*>(emb);

    float warp_loss = 0.0f;   // meaningful on lane 0 only

    int p  = warp_global;
    int ia = 0, ib = 0;
    if (p < P) { ia = __ldg(pair_a + p); ib = __ldg(pair_b + p); }

    while (p < P) {
        // Prefetch next pair's indices (hides idx->row dependent chain).
        const int p_next = p + warp_stride;
        int ia_next = 0, ib_next = 0;
        if (p_next < P) {
            ia_next = __ldg(pair_a + p_next);
            ib_next = __ldg(pair_b + p_next);
        }

        const float4* __restrict__ ra = embv + (size_t)ia * VEC_PER_ROW;
        const float4* __restrict__ rb = embv + (size_t)ib * VEC_PER_ROW;

        // 8 independent 16B L2-only loads (512B/warp each, fully coalesced).
        float4 va[4], vb[4];
        #pragma unroll
        for (int k = 0; k < 4; ++k) {
            va[k] = __ldcg(ra + lane + k * 32);
            vb[k] = __ldcg(rb + lane + k * 32);
        }

        // ||a-b||^2 per lane.
        float s = 0.0f;
        #pragma unroll
        for (int k = 0; k < 4; ++k) {
            float dx = va[k].x - vb[k].x;
            float dy = va[k].y - vb[k].y;
            float dz = va[k].z - vb[k].z;
            float dw = va[k].w - vb[k].w;
            s += dx * dx + dy * dy + dz * dz + dw * dw;
        }

        // Warp tree reduction (5 shfl).
        #pragma unroll
        for (int off = 16; off > 0; off >>= 1)
            s += __shfl_xor_sync(0xFFFFFFFFu, s, off);

        if (lane == 0) {
            float sq = fmaxf(s, 1e-12f);
            float d = sqrtf(sq);
            float i = (float)__ldg(pair_same + p);
            float h = fmaxf(0.0f, 1.0f - d);
            warp_loss += (1.0f - i) * h * h + i * d * d;
        }

        p  = p_next;
        ia = ia_next;
        ib = ib_next;
    }

    // Block reduction of per-warp losses.
    __shared__ float s_loss[WARPS_PER_BLOCK];
    __shared__ bool  s_is_last;
    if (lane == 0) s_loss[warp_id] = warp_loss;
    __syncthreads();

    if (threadIdx.x == 0) {
        float acc = 0.0f;
        #pragma unroll
        for (int w = 0; w < WARPS_PER_BLOCK; ++w) acc += s_loss[w];
        g_partials[blockIdx.x] = acc;
        unsigned int prev = atom_add_acqrel(&g_counter, 1u);  // release-orders store
        s_is_last = (prev == gridDim.x - 1);
        if (s_is_last) atomicExch(&g_counter, 0u);  // replay-safe self-reset
    }
    __syncthreads();

    // Last block: deterministic final reduction in fixed index order.
    if (s_is_last) {
        __shared__ float s_fin[THREADS_PER_BLOCK];
        float acc = 0.0f;
        for (int i = threadIdx.x; i < (int)gridDim.x; i += THREADS_PER_BLOCK)
            acc += g_partials[i];
        s_fin[threadIdx.x] = acc;
        __syncthreads();
        #pragma unroll
        for (int off = THREADS_PER_BLOCK / 2; off > 0; off >>= 1) {
            if (threadIdx.x < off) s_fin[threadIdx.x] += s_fin[threadIdx.x + off];
            __syncthreads();
        }
        if (threadIdx.x == 0)
            out[0] = s_fin[0] / ((float)P + 1e-10f);
    }
}

extern "C" void kernel_launch(void* const* d_in, const int* in_sizes, int n_in,
                              void* d_out, int out_size)
{
    const float* emb       = (const float*)d_in[0];
    const int*   pair_a    = (const int*)d_in[1];
    const int*   pair_b    = (const int*)d_in[2];
    const int*   pair_same = (const int*)d_in[3];
    float*       out       = (float*)d_out;

    const int P = in_sizes[1];  // element count of pair_a

    // Single balanced wave: at P=32768 -> 1024 blocks, exactly 4 pairs/warp.
    int warps_needed = (P + 3) / 4;  // target ~4 pairs per warp
    int num_blocks = (warps_needed + WARPS_PER_BLOCK - 1) / WARPS_PER_BLOCK;
    if (num_blocks > BLOCKS_TARGET) num_blocks = BLOCKS_TARGET;
    if (num_blocks < 1) num_blocks = 1;

    contrastive_fused_kernel<<<num_blocks, THREADS_PER_BLOCK>>>(
        emb, pair_a, pair_b, pair_same, out, P);
}